// round 16
// baseline (speedup 1.0000x reference)
#include <cuda_runtime.h>
#include <cuda_bf16.h>
#include <math.h>
#include <stdint.h>

#define T_DIM 512
#define B_DIM 64
#define IC 512
#define HC 512
#define L_DIM 2
#define K1 1024      // IC + HC (weight row stride)
#define N1 1024      // 2 * HC
#define NB 128       // serial blocks (1 CTA/SM, co-resident)
#define NT 512       // serial threads per block (16 warps)

#define M_ALL (T_DIM * B_DIM)          // 32768
#define N_ALL (N1 + HC)                // 1536

#define OUT_ACT ((size_t)T_DIM * B_DIM * HC)

// ---------------- device-global scratch (allocation-free rule) ----------------
__device__ float g_act [(size_t)T_DIM * B_DIM * HC];
__device__ float g_pre1[(size_t)T_DIM * B_DIM * N1];
__device__ float g_pre2[(size_t)T_DIM * B_DIM * HC];
// double-buffered recurrence state (write buf t&1, read buf (t&1)^1)
__device__ float g_h [2][B_DIM * HC];
__device__ float g_z [2][B_DIM * HC];
__device__ __nv_bfloat16 g_hh [2][B_DIM * HC];
__device__ __nv_bfloat16 g_hl [2][B_DIM * HC];
__device__ __nv_bfloat16 g_rhh[2][B_DIM * HC];
__device__ __nv_bfloat16 g_rhl[2][B_DIM * HC];
__device__ __nv_bfloat16 g_ahi[(size_t)M_ALL * IC];
__device__ __nv_bfloat16 g_alo[(size_t)M_ALL * IC];
__device__ __nv_bfloat16 g_whi[(size_t)N_ALL * IC];
__device__ __nv_bfloat16 g_wlo[(size_t)N_ALL * IC];
// flags: per half (A=0,B=1)
__device__ unsigned g_f1[2 * 64];      // [half][bg1 2][jg1 32] phase-1 done
__device__ unsigned g_f2[2 * 64];      // [half][bg2 4][jg2 16] phase-2 done
__device__ unsigned g_bar_cnt = 0;
__device__ unsigned g_bar_gen = 0;
__device__ unsigned g_dead    = 0;

__device__ __forceinline__ unsigned ld_u32_cg(const unsigned* p) {
    unsigned v;
    asm volatile("ld.global.cg.u32 %0, [%1];" : "=r"(v) : "l"(p) : "memory");
    return v;
}
__device__ __forceinline__ unsigned ld_acq(const unsigned* p) {
    unsigned v;
    asm volatile("ld.acquire.gpu.u32 %0, [%1];" : "=r"(v) : "l"(p) : "memory");
    return v;
}
__device__ __forceinline__ void st_rel(unsigned* p, unsigned v) {
    asm volatile("st.release.gpu.u32 [%0], %1;" :: "l"(p), "r"(v) : "memory");
}

// Full grid barrier (round-10 proven) — used ONCE per launch, after init.
__device__ __forceinline__ void grid_bar(unsigned target) {
    __syncthreads();
    if (threadIdx.x == 0) {
        if (ld_u32_cg(&g_dead) == 0u) {
            __threadfence();
            unsigned t = atomicAdd(&g_bar_cnt, 1u);
            if (t == NB - 1) {
                g_bar_cnt = 0;
                __threadfence();
                atomicExch(&g_bar_gen, target);
            } else {
                int it = 0;
                while (ld_u32_cg(&g_bar_gen) != target) {
                    if (++it > (1 << 20)) { atomicExch(&g_dead, 1u); break; }
                }
            }
            __threadfence();
        }
    }
    __syncthreads();
}

// Per-warp flag wait: lanes with mine=true each poll one flag (acquire);
// warp proceeds when all are >= ep. Bounded spin -> terminating wrong answer.
__device__ __forceinline__ void warp_wait(const unsigned* fp, bool mine, unsigned ep) {
    if (ld_u32_cg(&g_dead) == 0u) {
        int it = 0;
        for (;;) {
            unsigned v = mine ? ld_acq(fp) : ep;
            bool ok = !mine || (int)(v - ep) >= 0;
            if (__all_sync(0xffffffffu, ok)) break;
            if (++it > (1 << 20)) {
                if ((threadIdx.x & 31) == 0) st_rel(&g_dead, 1u);
                break;
            }
        }
    }
    __syncwarp();
}

// ---------------- fp32 -> (bf16 hi, bf16 lo) split ----------------
__device__ __forceinline__ void split4(float4 v, uint2& hi, uint2& lo) {
    __nv_bfloat16 h0 = __float2bfloat16_rn(v.x);
    __nv_bfloat16 h1 = __float2bfloat16_rn(v.y);
    __nv_bfloat16 h2 = __float2bfloat16_rn(v.z);
    __nv_bfloat16 h3 = __float2bfloat16_rn(v.w);
    __nv_bfloat16 l0 = __float2bfloat16_rn(v.x - __bfloat162float(h0));
    __nv_bfloat16 l1 = __float2bfloat16_rn(v.y - __bfloat162float(h1));
    __nv_bfloat16 l2 = __float2bfloat16_rn(v.z - __bfloat162float(h2));
    __nv_bfloat16 l3 = __float2bfloat16_rn(v.w - __bfloat162float(h3));
    hi.x = (unsigned)__bfloat16_as_ushort(h0) | ((unsigned)__bfloat16_as_ushort(h1) << 16);
    hi.y = (unsigned)__bfloat16_as_ushort(h2) | ((unsigned)__bfloat16_as_ushort(h3) << 16);
    lo.x = (unsigned)__bfloat16_as_ushort(l0) | ((unsigned)__bfloat16_as_ushort(l1) << 16);
    lo.y = (unsigned)__bfloat16_as_ushort(l2) | ((unsigned)__bfloat16_as_ushort(l3) << 16);
}

__device__ __forceinline__ void split1(float v, __nv_bfloat16& hi, __nv_bfloat16& lo) {
    hi = __float2bfloat16_rn(v);
    lo = __float2bfloat16_rn(v - __bfloat162float(hi));
}

__global__ void __launch_bounds__(256)
conv_act(const float* __restrict__ x, int l)
{
    const float* lin = (l == 0) ? x : g_act;
    size_t i = (size_t)blockIdx.x * 256 + threadIdx.x;
    float4 v = ((const float4*)lin)[i];
    uint2 hi, lo;
    split4(v, hi, lo);
    ((uint2*)g_ahi)[i] = hi;
    ((uint2*)g_alo)[i] = lo;
}

__global__ void __launch_bounds__(256)
conv_w(const float* __restrict__ W1, const float* __restrict__ W2, int l)
{
    size_t i = (size_t)blockIdx.x * 256 + threadIdx.x;
    int n  = (int)(i >> 7);
    int k4 = (int)(i & 127);
    const float* src = (n < N1)
        ? (W1 + (size_t)l * N1 * K1 + (size_t)n * K1 + k4 * 4)
        : (W2 + (size_t)l * HC * K1 + (size_t)(n - N1) * K1 + k4 * 4);
    float4 v = *(const float4*)src;
    uint2 hi, lo;
    split4(v, hi, lo);
    ((uint2*)g_whi)[(size_t)n * 128 + k4] = hi;
    ((uint2*)g_wlo)[(size_t)n * 128 + k4] = lo;
}

// =====================================================================
// mma hoist: 128x128x32 tile (halves A L2 re-reads vs R13). Per-element
// accumulation order unchanged. 8 warps = 4m x 2n of 32x64 warp tiles.
// =====================================================================
#define MBM 128
#define MBN 128
#define MBK 32
#define SAPAD 40

__device__ __forceinline__ void mma16816(float* c, const unsigned* a, const unsigned* b) {
    asm volatile(
        "mma.sync.aligned.m16n8k16.row.col.f32.bf16.bf16.f32 "
        "{%0,%1,%2,%3}, {%4,%5,%6,%7}, {%8,%9}, {%0,%1,%2,%3};\n"
        : "+f"(c[0]), "+f"(c[1]), "+f"(c[2]), "+f"(c[3])
        : "r"(a[0]), "r"(a[1]), "r"(a[2]), "r"(a[3]), "r"(b[0]), "r"(b[1]));
}

__global__ void __launch_bounds__(256)
mma_hoist(const float* __restrict__ b1, const float* __restrict__ b2, int l)
{
    __shared__ __nv_bfloat16 sA[2][MBM][SAPAD];
    __shared__ __nv_bfloat16 sB[2][MBN][SAPAD];

    const int bn  = blockIdx.x;            // 0..11
    const int m0  = blockIdx.y * MBM;
    const int tid = threadIdx.x;
    const int wid = tid >> 5, lane = tid & 31;
    const int wm  = wid & 3;               // m: wm*32
    const int wn  = wid >> 2;              // n: wn*64

    float* outp;  const float* bp;  int nstr, n0, wrow0;
    if (bn < 8) { n0 = bn * MBN;       wrow0 = n0;      outp = g_pre1; nstr = N1; bp = b1 + l * N1 + n0; }
    else        { n0 = (bn - 8) * MBN; wrow0 = N1 + n0; outp = g_pre2; nstr = HC; bp = b2 + l * HC + n0; }

    const __nv_bfloat16* segA[3] = { g_ahi, g_ahi, g_alo };
    const __nv_bfloat16* segW[3] = { g_whi, g_wlo, g_whi };

    const int ar = tid >> 1;               // 0..127 (row)
    const int aq = (tid & 1) * 16;         // half-offset: 0 or 16

    float acc[2][8][4];
    #pragma unroll
    for (int mt = 0; mt < 2; ++mt)
        #pragma unroll
        for (int nt = 0; nt < 8; ++nt)
            #pragma unroll
            for (int q = 0; q < 4; ++q) acc[mt][nt][q] = 0.f;

    {
        const __nv_bfloat16* A = segA[0];
        const __nv_bfloat16* W = segW[0];
        uint4 a0 = *(const uint4*)(A + (size_t)(m0 + ar) * IC + aq);
        uint4 a1 = *(const uint4*)(A + (size_t)(m0 + ar) * IC + aq + 8);
        uint4 w0 = *(const uint4*)(W + (size_t)(wrow0 + ar) * IC + aq);
        uint4 w1 = *(const uint4*)(W + (size_t)(wrow0 + ar) * IC + aq + 8);
        *(uint4*)&sA[0][ar][aq]     = a0;
        *(uint4*)&sA[0][ar][aq + 8] = a1;
        *(uint4*)&sB[0][ar][aq]     = w0;
        *(uint4*)&sB[0][ar][aq + 8] = w1;
    }
    __syncthreads();

    const int NIT = 48;
    for (int it = 0; it < NIT; ++it) {
        const int cur = it & 1;
        const bool more = (it + 1) < NIT;
        uint4 na0, na1, nw0, nw1;
        if (more) {
            int seg = (it + 1) >> 4;
            int kt  = ((it + 1) & 15) * MBK;
            const __nv_bfloat16* A = segA[seg];
            const __nv_bfloat16* W = segW[seg];
            na0 = *(const uint4*)(A + (size_t)(m0 + ar) * IC + kt + aq);
            na1 = *(const uint4*)(A + (size_t)(m0 + ar) * IC + kt + aq + 8);
            nw0 = *(const uint4*)(W + (size_t)(wrow0 + ar) * IC + kt + aq);
            nw1 = *(const uint4*)(W + (size_t)(wrow0 + ar) * IC + kt + aq + 8);
        }

        #pragma unroll
        for (int ks = 0; ks < MBK; ks += 16) {
            const int kb = ks + (lane & 3) * 2;
            unsigned af[2][4], bf[8][2];
            #pragma unroll
            for (int mt = 0; mt < 2; ++mt) {
                int r = wm * 32 + mt * 16 + (lane >> 2);
                af[mt][0] = *(const unsigned*)&sA[cur][r][kb];
                af[mt][1] = *(const unsigned*)&sA[cur][r + 8][kb];
                af[mt][2] = *(const unsigned*)&sA[cur][r][kb + 8];
                af[mt][3] = *(const unsigned*)&sA[cur][r + 8][kb + 8];
            }
            #pragma unroll
            for (int nt = 0; nt < 8; ++nt) {
                int c = wn * 64 + nt * 8 + (lane >> 2);
                bf[nt][0] = *(const unsigned*)&sB[cur][c][kb];
                bf[nt][1] = *(const unsigned*)&sB[cur][c][kb + 8];
            }
            #pragma unroll
            for (int mt = 0; mt < 2; ++mt)
                #pragma unroll
                for (int nt = 0; nt < 8; ++nt)
                    mma16816(acc[mt][nt], af[mt], bf[nt]);
        }

        if (more) {
            const int nxt = cur ^ 1;
            *(uint4*)&sA[nxt][ar][aq]     = na0;
            *(uint4*)&sA[nxt][ar][aq + 8] = na1;
            *(uint4*)&sB[nxt][ar][aq]     = nw0;
            *(uint4*)&sB[nxt][ar][aq + 8] = nw1;
            __syncthreads();
        }
    }

    #pragma unroll
    for (int mt = 0; mt < 2; ++mt) {
        #pragma unroll
        for (int nt = 0; nt < 8; ++nt) {
            int r  = m0 + wm * 32 + mt * 16 + (lane >> 2);
            int cl = wn * 64 + nt * 8 + (lane & 3) * 2;
            float bx = bp[cl], by = bp[cl + 1];
            float2 o0 = { acc[mt][nt][0] + bx, acc[mt][nt][1] + by };
            float2 o1 = { acc[mt][nt][2] + bx, acc[mt][nt][3] + by };
            *(float2*)(outp + (size_t)r * nstr + n0 + cl)       = o0;
            *(float2*)(outp + (size_t)(r + 8) * nstr + n0 + cl) = o1;
        }
    }
}

// =====================================================================
// Serial kernel: R14 mirrored two-group structure + compute verbatim.
// Per-warp flag waits + per-warp k-slice staging; h/rh/z double-buffered.
// WAR FIX vs R15: P2 wait covers ALL 32 f1 producers collectively
// (jg1 in {2ks,2ks+1,16+2ks,16+2ks+1} per warp) since z-gate P1 CTAs
// also stage-read g_h.
// =====================================================================
#define WS 520      // smem row stride in halfs
#define OFF_W1H 0
#define OFF_W1L 33280
#define OFF_W2H 66560
#define OFF_W2L 99840
#define OFF_HH  133120
#define OFF_HL  149760
#define OFF_RED 166400
#define SER_SMEM_BYTES 182784

__device__ __forceinline__ uint32_t s2u(const void* p) {
    return (uint32_t)__cvta_generic_to_shared(p);
}
__device__ __forceinline__ void ldsm_x4(unsigned* r, uint32_t addr) {
    asm volatile("ldmatrix.sync.aligned.m8n8.x4.shared.b16 {%0,%1,%2,%3}, [%4];"
                 : "=r"(r[0]), "=r"(r[1]), "=r"(r[2]), "=r"(r[3]) : "r"(addr));
}

__global__ void __launch_bounds__(NT, 1)
serial_kernel(const float* __restrict__ hiddens,
              const float* __restrict__ W1, const float* __restrict__ W2,
              float* __restrict__ out, int l)
{
    extern __shared__ char smc[];
    __nv_bfloat16* sW1h = (__nv_bfloat16*)(smc + OFF_W1H);
    __nv_bfloat16* sW1l = (__nv_bfloat16*)(smc + OFF_W1L);
    __nv_bfloat16* sW2h = (__nv_bfloat16*)(smc + OFF_W2H);
    __nv_bfloat16* sW2l = (__nv_bfloat16*)(smc + OFF_W2L);
    __nv_bfloat16* sHh  = (__nv_bfloat16*)(smc + OFF_HH);
    __nv_bfloat16* sHl  = (__nv_bfloat16*)(smc + OFF_HL);
    float*         red  = (float*)(smc + OFF_RED);   // [ks 8][jt 4][lane 32][4]

    const int tid  = threadIdx.x;
    const int bid  = blockIdx.x;
    const int wp   = tid >> 5;
    const int lane = tid & 31;
    const int ks   = wp >> 1;   // k-slice 0..7 (64 k each)
    const int jp   = wp & 1;    // pair member: 0 = hi stager, 1 = lo stager

    // ---- mirrored role assignment ----
    const int p1half = (bid < 64) ? 0 : 1;
    const int p1base = p1half * 32;
    const int p2half = 1 - p1half;
    const int p2base = p2half * 32;
    const int r   = bid & 63;
    const int jg1 = r >> 1;    // 0..31
    const int bg1 = r & 1;     // 0..1
    const int jg2 = r >> 2;    // 0..15
    const int bg2 = r & 3;     // 0..3

    float* lout = (l == 0) ? g_act : out;

    const int jl1 = tid & 31, bl1 = tid >> 5;           // phase1: 32j x 16b
    const int j1  = jg1 * 32 + jl1;
    const int b1o = p1base + bg1 * 16 + bl1;
    const int jl2 = tid & 31, bl2 = (tid >> 5) & 7;     // phase2: 32j x 8b
    const int j2  = jg2 * 32 + jl2;
    const int b2o = p2base + bg2 * 8 + bl2;
    const bool p2own = (tid < 256);

    const int lf1 = (bl1 & 7) * 4 + ((jl1 & 7) >> 1);
    const int cc1 = (jl1 & 1) + ((bl1 >> 3) << 1);
    const int jt1 = jl1 >> 3;
    const int lf2 = bl2 * 4 + ((jl2 & 7) >> 1);
    const int cc2 = jl2 & 1;
    const int jt2 = jl2 >> 3;

    // ---- stage bf16-split weights once per layer ----
    for (int idx = tid; idx < 32 * 128; idx += NT) {
        int jl = idx >> 7, k4 = idx & 127;
        float4 v1 = *(const float4*)&W1[((size_t)l * N1 + jg1 * 32 + jl) * K1 + IC + k4 * 4];
        float4 v2 = *(const float4*)&W2[((size_t)l * HC + jg2 * 32 + jl) * K1 + IC + k4 * 4];
        uint2 hi, lo;
        split4(v1, hi, lo);
        *(uint2*)&sW1h[jl * WS + k4 * 4] = hi;
        *(uint2*)&sW1l[jl * WS + k4 * 4] = lo;
        split4(v2, hi, lo);
        *(uint2*)&sW2h[jl * WS + k4 * 4] = hi;
        *(uint2*)&sW2l[jl * WS + k4 * 4] = lo;
    }

    // Init hidden state into READ buffer of t=0 (buf 1), reset own flags
    { int i = bid * NT + tid;
      if (i < B_DIM * HC) {
          float v = hiddens[l * HC + (i & (HC - 1))];
          g_h[1][i] = v;
          __nv_bfloat16 hi, lo;
          split1(v, hi, lo);
          g_hh[1][i] = hi;  g_hl[1][i] = lo;
      } }
    if (tid == 0) {
        g_f1[p1half * 64 + bg1 * 32 + jg1] = 0;
        g_f2[p2half * 64 + bg2 * 16 + jg2] = 0;
    }

    unsigned ep = ld_u32_cg(&g_bar_gen);
    grid_bar(++ep);      // init + flag resets visible grid-wide

    unsigned* f1_own = &g_f1[p1half * 64 + bg1 * 32 + jg1];
    unsigned* f2_own = &g_f2[p2half * 64 + bg2 * 16 + jg2];

    // per-lane P1 flag address: h-producer f2 of my k-slice (4 flags) +
    // warp0 lanes 4..5 cover hv's column flag (jg2 = jg1, r-CTAs only).
    const unsigned* p1_fp;
    bool p1_mine;
    {
        int nf = (wp == 0 && jg1 < 16) ? 6 : 4;
        int idx;
        if (lane < 4)      idx = p1half * 64 + (2 * bg1 + (lane & 1)) * 16 + (2 * ks + (lane >> 1));
        else if (lane < 6) idx = p1half * 64 + (2 * bg1 + (lane - 4)) * 16 + jg1;
        else               idx = p1half * 64;
        p1_fp = &g_f2[idx];
        p1_mine = lane < nf;
    }
    // per-lane P2 flag address: rh-producer f1 (r-CTAs, 2 flags) +
    // z-gate stagers' f1 (WAR on g_h; 2 flags) + warp0 z-column flag.
    // Collectively all 32 jg1 of bg1 = bg2>>1 are covered -> g_h WAR safe.
    const unsigned* p2_fp;
    bool p2_mine;
    {
        int nf = (wp == 0) ? 5 : 4;
        int idx;
        if (lane < 2)      idx = p2half * 64 + (bg2 >> 1) * 32 + (2 * ks + lane);        // rh RAW
        else if (lane < 4) idx = p2half * 64 + (bg2 >> 1) * 32 + 16 + (2 * ks + lane - 2); // z-CTA h-WAR
        else if (lane < 5) idx = p2half * 64 + (bg2 >> 1) * 32 + 16 + jg2;               // z RAW
        else               idx = p2half * 64;
        p2_fp = &g_f1[idx];
        p2_mine = lane < nf;
    }

    const int lrow = (lane & 7) + ((lane >> 3) & 1) * 8;   // 0..15
    const int lkof = (lane >> 4) << 3;                     // 0 or 8
    const int k0   = ks * 64;

    for (int t = 0; t < T_DIM; ++t) {
        const unsigned sep = (unsigned)(t + 1);
        const int bw = t & 1;       // write buffer this step
        const int br = bw ^ 1;      // read buffer (state from t-1)

        // t-only prefetch (no recurrence dependency)
        float pre1v = __ldcg(&g_pre1[((size_t)t * B_DIM + b1o) * N1 + j1]);
        float pre2v = 0.f;
        if (p2own) pre2v = __ldcg(&g_pre2[((size_t)t * B_DIM + b2o) * HC + j2]);

        // ---- P1: per-warp wait on my h-producer flags ----
        if (t > 0) warp_wait(p1_fp, p1_mine, sep - 1);

        // ---- per-warp stage of my k-slice (pair: jp=0 hi, jp=1 lo) ----
        {
            const __nv_bfloat16* src = jp ? g_hl[br] : g_hh[br];
            __nv_bfloat16* dst = jp ? sHl : sHh;
            #pragma unroll
            for (int q = 0; q < 4; ++q) {
                int i = lane + 32 * q;            // 0..127
                int row = i >> 3, c8 = i & 7;
                uint4 v = __ldcg((const uint4*)&src[(size_t)(p1base + bg1 * 16 + row) * HC + k0 + c8 * 8]);
                *(uint4*)&dst[row * WS + k0 + c8 * 8] = v;
            }
        }
        asm volatile("bar.sync %0, 64;" :: "r"(1 + ks) : "memory");

        // ---- Phase 1 compute: h @ W1h^T via LDSM + mma (verbatim) ----
        {
            float acc[2][4];
            #pragma unroll
            for (int jj = 0; jj < 2; ++jj)
                #pragma unroll
                for (int q = 0; q < 4; ++q) acc[jj][q] = 0.f;
            #pragma unroll
            for (int cc = 0; cc < 4; ++cc) {
                int kb0 = ks * 64 + cc * 16 + lkof;
                unsigned ah[4], al[4], wh[4], wl[4];
                ldsm_x4(ah, s2u(&sHh[lrow * WS + kb0]));
                ldsm_x4(al, s2u(&sHl[lrow * WS + kb0]));
                ldsm_x4(wh, s2u(&sW1h[(jp * 16 + lrow) * WS + kb0]));
                ldsm_x4(wl, s2u(&sW1l[(jp * 16 + lrow) * WS + kb0]));
                #pragma unroll
                for (int jj = 0; jj < 2; ++jj) {
                    unsigned bh[2] = { wh[jj], wh[jj + 2] };
                    unsigned bl_[2] = { wl[jj], wl[jj + 2] };
                    mma16816(acc[jj], ah, bh);
                    mma16816(acc[jj], ah, bl_);
                    mma16816(acc[jj], al, bh);
                }
            }
            #pragma unroll
            for (int jj = 0; jj < 2; ++jj)
                *(float4*)&red[((ks * 4 + jp * 2 + jj) * 32 + lane) * 4] =
                    *(float4*)acc[jj];
        }
        __syncthreads();   // red ready; also publishes warp0's hv-flag acquire

        // ---- Phase 1 epilogue: r,z; rh/z -> write buffer ----
        {
            float s = 0.f;
            #pragma unroll
            for (int kq = 0; kq < 8; ++kq)
                s += red[((kq * 4 + jt1) * 32 + lf1) * 4 + cc1];
            float pre = s + pre1v;
            float sg  = __fdividef(1.f, 1.f + __expf(-pre));
            if (jg1 < 16) {
                float hv = __ldcg(&g_h[br][b1o * HC + j1]);
                float rhv = sg * hv;
                __nv_bfloat16 hi, lo;
                split1(rhv, hi, lo);
                g_rhh[bw][b1o * HC + j1] = hi;
                g_rhl[bw][b1o * HC + j1] = lo;
            } else {
                g_z[bw][b1o * HC + (j1 - HC)] = sg;
            }
        }
        __syncthreads();   // all rh/z stores done
        if (tid == 0) st_rel(f1_own, sep);

        // ---- P2: per-warp wait on my rh/z-producer + h-WAR flags ----
        warp_wait(p2_fp, p2_mine, sep);

        // ---- per-warp stage of rh k-slice (rows 0..7) ----
        {
            const __nv_bfloat16* src = jp ? g_rhl[bw] : g_rhh[bw];
            __nv_bfloat16* dst = jp ? sHl : sHh;
            #pragma unroll
            for (int q = 0; q < 2; ++q) {
                int i = lane + 32 * q;            // 0..63
                int row = i >> 3, c8 = i & 7;
                uint4 v = __ldcg((const uint4*)&src[(size_t)(p2base + bg2 * 8 + row) * HC + k0 + c8 * 8]);
                *(uint4*)&dst[row * WS + k0 + c8 * 8] = v;
            }
        }
        asm volatile("bar.sync %0, 64;" :: "r"(1 + ks) : "memory");

        // ---- Phase 2 compute (verbatim; rows 8..15 stale/unused) ----
        {
            float acc[2][4];
            #pragma unroll
            for (int jj = 0; jj < 2; ++jj)
                #pragma unroll
                for (int q = 0; q < 4; ++q) acc[jj][q] = 0.f;
            #pragma unroll
            for (int cc = 0; cc < 4; ++cc) {
                int kb0 = ks * 64 + cc * 16 + lkof;
                unsigned ah[4], al[4], wh[4], wl[4];
                ldsm_x4(ah, s2u(&sHh[lrow * WS + kb0]));
                ldsm_x4(al, s2u(&sHl[lrow * WS + kb0]));
                ldsm_x4(wh, s2u(&sW2h[(jp * 16 + lrow) * WS + kb0]));
                ldsm_x4(wl, s2u(&sW2l[(jp * 16 + lrow) * WS + kb0]));
                #pragma unroll
                for (int jj = 0; jj < 2; ++jj) {
                    unsigned bh[2] = { wh[jj], wh[jj + 2] };
                    unsigned bl_[2] = { wl[jj], wl[jj + 2] };
                    mma16816(acc[jj], ah, bh);
                    mma16816(acc[jj], ah, bl_);
                    mma16816(acc[jj], al, bh);
                }
            }
            #pragma unroll
            for (int jj = 0; jj < 2; ++jj)
                *(float4*)&red[((ks * 4 + jp * 2 + jj) * 32 + lane) * 4] =
                    *(float4*)acc[jj];
        }
        __syncthreads();   // red ready; publishes warp0's z-flag acquire

        // ---- Phase 2 epilogue: h update -> write buffer ----
        if (p2own) {
            float s = 0.f;
            #pragma unroll
            for (int kq = 0; kq < 8; ++kq)
                s += red[((kq * 4 + jt2) * 32 + lf2) * 4 + cc2];
            float zv  = __ldcg(&g_z[bw][b2o * HC + j2]);
            float hov = __ldcg(&g_h[br][b2o * HC + j2]);   // self-written t-1
            float x2v = s + pre2v;
            float gg  = 1.f - __fdividef(2.f, __expf(2.f * x2v) + 1.f);
            float hn  = zv * hov + (1.f - zv) * gg;
            g_h[bw][b2o * HC + j2] = hn;
            __nv_bfloat16 hi, lo;
            split1(hn, hi, lo);
            g_hh[bw][b2o * HC + j2] = hi;
            g_hl[bw][b2o * HC + j2] = lo;
            lout[((size_t)t * B_DIM + b2o) * HC + j2] = hn;
            if (t == T_DIM - 1)
                out[OUT_ACT + (size_t)l * B_DIM * HC + b2o * HC + j2] = hn;
        }
        __syncthreads();   // all h stores done
        if (tid == 0) st_rel(f2_own, sep);
    }
}

extern "C" void kernel_launch(void* const* d_in, const int* in_sizes, int n_in,
                              void* d_out, int out_size) {
    const float* x       = (const float*)d_in[0];
    const float* hiddens = (const float*)d_in[1];
    const float* W1      = (const float*)d_in[2];
    const float* b1      = (const float*)d_in[3];
    const float* W2      = (const float*)d_in[4];
    const float* b2      = (const float*)d_in[5];
    float* out = (float*)d_out;

    cudaFuncSetAttribute(serial_kernel,
                         cudaFuncAttributeMaxDynamicSharedMemorySize,
                         SER_SMEM_BYTES);

    for (int l = 0; l < L_DIM; ++l) {
        conv_act<<<M_ALL * IC / 4 / 256, 256>>>(x, l);
        conv_w  <<<N_ALL * IC / 4 / 256, 256>>>(W1, W2, l);
        mma_hoist<<<dim3(12, M_ALL / MBM), 256>>>(b1, b2, l);
        serial_kernel<<<NB, NT, SER_SMEM_BYTES>>>(hiddens, W1, W2, out, l);
    }
}